// round 15
// baseline (speedup 1.0000x reference)
#include <cuda_runtime.h>
#include <cuda_fp16.h>
#include <cuda_bf16.h>
#include <stdint.h>
#include <math.h>

#define TINV 14.2857142857142857f   /* 1 / 0.07 */
#define K1E  20.6099291083577f      /* TINV * log2(e) */

// -------- scratch (no allocations allowed) --------
static __device__ __half g_x16[8192 * 2048];
static __device__ __half g_w0t[2048 * 2048];
static __device__ __half g_w1e[2048 * 2048];
static __device__ __half g_w2t[128 * 2048];
static __device__ __half g_w12[128 * 2048];
static __device__ float  g_w12p[8 * 128 * 2048];
static __device__ __half g_a0[8192 * 2048];
static __device__ float  g_featp[2 * 8192 * 128];
static __device__ float  g_b12[128];
static __device__ float  g_feat[8192 * 128];
static __device__ __nv_bfloat16 g_fhi[8192 * 128];
static __device__ __nv_bfloat16 g_flo[8192 * 128];
static __device__ float g_pos[8192];
static __device__ float g_S[8192];

// ======================= PTX helpers (baseline ISA only) =====================
__device__ __forceinline__ void cp_async16(unsigned int saddr, const void* gptr) {
    asm volatile("cp.async.ca.shared.global [%0], [%1], 16;" :: "r"(saddr), "l"(gptr));
}
__device__ __forceinline__ void cp_commit() {
    asm volatile("cp.async.commit_group;");
}
__device__ __forceinline__ unsigned int smem_u32(const void* p) {
    unsigned int a;
    asm("{ .reg .u64 t; cvta.to.shared.u64 t, %1; cvt.u32.u64 %0, t; }" : "=r"(a) : "l"(p));
    return a;
}
__device__ __forceinline__ void ldmat4(unsigned int* r, unsigned int addr) {
    asm volatile("ldmatrix.sync.aligned.m8n8.x4.shared.b16 {%0,%1,%2,%3}, [%4];"
        : "=r"(r[0]), "=r"(r[1]), "=r"(r[2]), "=r"(r[3]) : "r"(addr));
}
__device__ __forceinline__ void hmma(float* d, const unsigned int* a,
                                     unsigned int b0, unsigned int b1) {
    asm volatile(
        "mma.sync.aligned.m16n8k16.row.col.f32.f16.f16.f32 "
        "{%0,%1,%2,%3}, {%4,%5,%6,%7}, {%8,%9}, {%0,%1,%2,%3};"
        : "+f"(d[0]), "+f"(d[1]), "+f"(d[2]), "+f"(d[3])
        : "r"(a[0]), "r"(a[1]), "r"(a[2]), "r"(a[3]), "r"(b0), "r"(b1));
}
__device__ __forceinline__ void bmma(float* d, const unsigned int* a,
                                     unsigned int b0, unsigned int b1) {
    asm volatile(
        "mma.sync.aligned.m16n8k16.row.col.f32.bf16.bf16.f32 "
        "{%0,%1,%2,%3}, {%4,%5,%6,%7}, {%8,%9}, {%0,%1,%2,%3};"
        : "+f"(d[0]), "+f"(d[1]), "+f"(d[2]), "+f"(d[3])
        : "r"(a[0]), "r"(a[1]), "r"(a[2]), "r"(a[3]), "r"(b0), "r"(b1));
}

// ======================= fp16 warp-MMA GEMM (128x128) ========================
// 5-stage cp.async ring + wait_group 3, ONE barrier per chunk, 2 CTAs/SM.
#define ROWB 80
#define F_A 0
#define F_B (128 * ROWB)            /* 10240 */
#define FSTAGE (2 * 128 * ROWB)     /* 20480 */
#define SMEM_BIAS 0
#define SMEM_STAGE0 1024
#define GEMM_SMEM (SMEM_STAGE0 + 5 * FSTAGE)   /* 103424 */
#define W12_SMEM  (SMEM_STAGE0 + 4 * FSTAGE)   /* 82944  */

template <bool RELU>
__global__ __launch_bounds__(256, 2) void gemm_f16(
    const __half* __restrict__ A, const __half* __restrict__ B,
    const float* __restrict__ bias, __half* __restrict__ C)
{
    extern __shared__ char smem[];
    const unsigned int sb = smem_u32(smem);
    const int tid  = threadIdx.x;
    const int lane = tid & 31;
    const int wid  = tid >> 5;
    const int wm   = wid >> 1;
    const int wn   = wid & 1;
    const int row0 = blockIdx.x * 128;
    const int col0 = blockIdx.y * 128;
    const int K = 2048;
    const int NKT = 64;

    if (tid < 128) ((float*)(smem + SMEM_BIAS))[tid] = bias[col0 + tid];

    const int srow = tid >> 1;
    const int shal = tid & 1;
    const __half* gA = A + (long)(row0 + srow) * K + shal * 16;
    const __half* gB = B + (long)(col0 + srow) * K + shal * 16;
    const unsigned int sro = srow * ROWB + shal * 32;

#define LOAD_STAGE(stg, k0) do { \
        cp_async16((stg) + F_A + sro,      gA + (k0)); \
        cp_async16((stg) + F_A + sro + 16, gA + (k0) + 8); \
        cp_async16((stg) + F_B + sro,      gB + (k0)); \
        cp_async16((stg) + F_B + sro + 16, gB + (k0) + 8); \
    } while (0)

#pragma unroll
    for (int b = 0; b < 4; b++) {
        LOAD_STAGE(sb + SMEM_STAGE0 + b * FSTAGE, b * 32);
        cp_commit();
    }

    float acc[2][8][4];
#pragma unroll
    for (int i = 0; i < 2; i++)
#pragma unroll
        for (int j = 0; j < 8; j++)
#pragma unroll
            for (int q = 0; q < 4; q++) acc[i][j][q] = 0.f;

    const unsigned int a_row  = lane & 15;
    const unsigned int a_koff = (lane >> 4) * 16;
    const unsigned int b_row  = (lane & 7) + ((lane >> 4) & 1) * 8;
    const unsigned int b_koff = ((lane >> 3) & 1) * 16;

    int st = 0, pf = 4;
    for (int kt = 0; kt < NKT; kt++) {
        const unsigned int stg = sb + SMEM_STAGE0 + st * FSTAGE;
        asm volatile("cp.async.wait_group 3;" ::: "memory");
        __syncthreads();

        if (kt + 4 < NKT) {
            const unsigned int pst = sb + SMEM_STAGE0 + pf * FSTAGE;
            LOAD_STAGE(pst, (kt + 4) * 32);
        }
        cp_commit();

#pragma unroll
        for (int s = 0; s < 2; s++) {
            const unsigned int kb = s * 32;
            unsigned int ah[2][4];
#pragma unroll
            for (int ma = 0; ma < 2; ma++) {
                unsigned int roff = (wm * 32 + ma * 16 + a_row) * ROWB + kb + a_koff;
                ldmat4(ah[ma], stg + F_A + roff);
            }
            unsigned int bh[4][4];
#pragma unroll
            for (int nb = 0; nb < 4; nb++) {
                unsigned int roff = (wn * 64 + nb * 16 + b_row) * ROWB + kb + b_koff;
                ldmat4(bh[nb], stg + F_B + roff);
            }
#pragma unroll
            for (int ma = 0; ma < 2; ma++)
#pragma unroll
                for (int na = 0; na < 8; na++)
                    hmma(acc[ma][na], ah[ma],
                         bh[na >> 1][(na & 1) * 2], bh[na >> 1][(na & 1) * 2 + 1]);
        }

        if (++st == 5) st = 0;
        if (++pf == 5) pf = 0;
    }

    const float* bs = (const float*)(smem + SMEM_BIAS);
    const int ccol = wn * 64;
#pragma unroll
    for (int ma = 0; ma < 2; ma++) {
#pragma unroll
        for (int na = 0; na < 8; na++) {
            int c  = ccol + na * 8 + (lane & 3) * 2;
            int r1 = row0 + wm * 32 + ma * 16 + (lane >> 2);
            int r2 = r1 + 8;
            float v0 = acc[ma][na][0] + bs[c];
            float v1 = acc[ma][na][1] + bs[c + 1];
            float v2 = acc[ma][na][2] + bs[c];
            float v3 = acc[ma][na][3] + bs[c + 1];
            if (RELU) {
                v0 = fmaxf(v0, 0.f); v1 = fmaxf(v1, 0.f);
                v2 = fmaxf(v2, 0.f); v3 = fmaxf(v3, 0.f);
            }
            *(__half2*)&C[(long)r1 * 2048 + col0 + c] = __floats2half2_rn(v0, v1);
            *(__half2*)&C[(long)r2 * 2048 + col0 + c] = __floats2half2_rn(v2, v3);
        }
    }
#undef LOAD_STAGE
}

// ======================= W12 split-K fp16 GEMM: grid (8, 16) =================
__global__ __launch_bounds__(256, 2) void gemm_w12(
    const __half* __restrict__ A, const __half* __restrict__ B,
    float* __restrict__ Cp)
{
    extern __shared__ char smem[];
    const unsigned int sb = smem_u32(smem);
    const int tid  = threadIdx.x;
    const int lane = tid & 31;
    const int wid  = tid >> 5;
    const int wm   = wid >> 1;
    const int wn   = wid & 1;
    const int col0 = blockIdx.y * 128;
    const int kbase = blockIdx.x * 256;
    const int K = 2048;
    const int NKT = 8;

    const int srow = tid >> 1;
    const int shal = tid & 1;
    const __half* gA = A + (long)srow * K + kbase + shal * 16;
    const __half* gB = B + (long)(col0 + srow) * K + kbase + shal * 16;
    const unsigned int sro = srow * ROWB + shal * 32;

#define LOAD_STAGE(stg, k0) do { \
        cp_async16((stg) + F_A + sro,      gA + (k0)); \
        cp_async16((stg) + F_A + sro + 16, gA + (k0) + 8); \
        cp_async16((stg) + F_B + sro,      gB + (k0)); \
        cp_async16((stg) + F_B + sro + 16, gB + (k0) + 8); \
    } while (0)

#pragma unroll
    for (int b = 0; b < 3; b++) {
        LOAD_STAGE(sb + SMEM_STAGE0 + b * FSTAGE, b * 32);
        cp_commit();
    }

    float acc[2][8][4];
#pragma unroll
    for (int i = 0; i < 2; i++)
#pragma unroll
        for (int j = 0; j < 8; j++)
#pragma unroll
            for (int q = 0; q < 4; q++) acc[i][j][q] = 0.f;

    const unsigned int a_row  = lane & 15;
    const unsigned int a_koff = (lane >> 4) * 16;
    const unsigned int b_row  = (lane & 7) + ((lane >> 4) & 1) * 8;
    const unsigned int b_koff = ((lane >> 3) & 1) * 16;

    for (int kt = 0; kt < NKT; kt++) {
        const unsigned int stg = sb + SMEM_STAGE0 + (kt & 3) * FSTAGE;
        asm volatile("cp.async.wait_group 2;" ::: "memory");
        __syncthreads();

        if (kt + 3 < NKT) {
            const unsigned int pst = sb + SMEM_STAGE0 + ((kt + 3) & 3) * FSTAGE;
            LOAD_STAGE(pst, (kt + 3) * 32);
        }
        cp_commit();

#pragma unroll
        for (int s = 0; s < 2; s++) {
            const unsigned int kb = s * 32;
            unsigned int ah[2][4];
#pragma unroll
            for (int ma = 0; ma < 2; ma++) {
                unsigned int roff = (wm * 32 + ma * 16 + a_row) * ROWB + kb + a_koff;
                ldmat4(ah[ma], stg + F_A + roff);
            }
            unsigned int bh[4][4];
#pragma unroll
            for (int nb = 0; nb < 4; nb++) {
                unsigned int roff = (wn * 64 + nb * 16 + b_row) * ROWB + kb + b_koff;
                ldmat4(bh[nb], stg + F_B + roff);
            }
#pragma unroll
            for (int ma = 0; ma < 2; ma++)
#pragma unroll
                for (int na = 0; na < 8; na++)
                    hmma(acc[ma][na], ah[ma],
                         bh[na >> 1][(na & 1) * 2], bh[na >> 1][(na & 1) * 2 + 1]);
        }
    }

    float* out = Cp + (long)blockIdx.x * 128 * 2048;
#pragma unroll
    for (int ma = 0; ma < 2; ma++) {
#pragma unroll
        for (int na = 0; na < 8; na++) {
            int c  = col0 + wn * 64 + na * 8 + (lane & 3) * 2;
            int r1 = wm * 32 + ma * 16 + (lane >> 2);
            int r2 = r1 + 8;
            *(float2*)&out[(long)r1 * 2048 + c] =
                make_float2(acc[ma][na][0], acc[ma][na][1]);
            *(float2*)&out[(long)r2 * 2048 + c] =
                make_float2(acc[ma][na][2], acc[ma][na][3]);
        }
    }
#undef LOAD_STAGE
}

// =========== fixed-order reduce of 8 W12 slices -> fp16 ======================
__global__ __launch_bounds__(256) void w12_reduce(
    const float* __restrict__ Cp, __half* __restrict__ T)
{
    int i = blockIdx.x * 256 + threadIdx.x;
    float4 s = ((const float4*)Cp)[i];
#pragma unroll
    for (int k = 1; k < 8; k++) {
        float4 p = ((const float4*)(Cp + (long)k * 128 * 2048))[i];
        s.x += p.x; s.y += p.y; s.z += p.z; s.w += p.w;
    }
    __half2 h0 = __floats2half2_rn(s.x, s.y);
    __half2 h1 = __floats2half2_rn(s.z, s.w);
    uint2 o = {*(unsigned int*)&h0, *(unsigned int*)&h1};
    ((uint2*)T)[i] = o;
}

// =================== head GEMM fp16 split-K: grid (2, 128), 4 stages =========
#define H_A 0
#define H_B (64 * ROWB)
#define H_STAGE (H_B + 128 * ROWB)
#define HEAD_SMEM (1024 + 4 * H_STAGE)

__global__ __launch_bounds__(256, 2) void gemm_head(
    const __half* __restrict__ A, const __half* __restrict__ B,
    float* __restrict__ Cp)
{
    extern __shared__ char smem[];
    const unsigned int sb = smem_u32(smem);
    const int tid  = threadIdx.x;
    const int lane = tid & 31;
    const int wid  = tid >> 5;
    const int wm   = wid >> 2;
    const int wn   = wid & 3;
    const int row0 = blockIdx.y * 64;
    const int kbase = blockIdx.x * 1024;
    const int K = 2048;
    const int NKT = 32;

    const int sar = tid >> 2;
    const int saq = tid & 3;
    const __half* gA = A + (long)(row0 + sar) * K + kbase + saq * 8;
    const unsigned int sra = sar * ROWB + saq * 16;
    const int sbr = tid >> 1;
    const int sbh = tid & 1;
    const __half* gB = B + (long)sbr * K + kbase + sbh * 16;
    const unsigned int srb = sbr * ROWB + sbh * 32;

#define H_LOAD(stg, k0) do { \
        cp_async16((stg) + H_A + sra, gA + (k0)); \
        cp_async16((stg) + H_B + srb,      gB + (k0)); \
        cp_async16((stg) + H_B + srb + 16, gB + (k0) + 8); \
    } while (0)

#pragma unroll
    for (int b = 0; b < 3; b++) {
        H_LOAD(sb + SMEM_STAGE0 + b * H_STAGE, b * 32);
        cp_commit();
    }

    float acc[2][4][4];
#pragma unroll
    for (int i = 0; i < 2; i++)
#pragma unroll
        for (int j = 0; j < 4; j++)
#pragma unroll
            for (int q = 0; q < 4; q++) acc[i][j][q] = 0.f;

    const unsigned int a_row  = lane & 15;
    const unsigned int a_koff = (lane >> 4) * 16;
    const unsigned int b_row  = (lane & 7) + ((lane >> 4) & 1) * 8;
    const unsigned int b_koff = ((lane >> 3) & 1) * 16;

    for (int kt = 0; kt < NKT; kt++) {
        const unsigned int stg = sb + SMEM_STAGE0 + (kt & 3) * H_STAGE;
        asm volatile("cp.async.wait_group 2;" ::: "memory");
        __syncthreads();

        if (kt + 3 < NKT) {
            const unsigned int pst = sb + SMEM_STAGE0 + ((kt + 3) & 3) * H_STAGE;
            H_LOAD(pst, (kt + 3) * 32);
        }
        cp_commit();

#pragma unroll
        for (int s = 0; s < 2; s++) {
            const unsigned int kb = s * 32;
            unsigned int ah[2][4];
#pragma unroll
            for (int ma = 0; ma < 2; ma++) {
                unsigned int roff = (wm * 32 + ma * 16 + a_row) * ROWB + kb + a_koff;
                ldmat4(ah[ma], stg + H_A + roff);
            }
            unsigned int bh[2][4];
#pragma unroll
            for (int nb = 0; nb < 2; nb++) {
                unsigned int roff = (wn * 32 + nb * 16 + b_row) * ROWB + kb + b_koff;
                ldmat4(bh[nb], stg + H_B + roff);
            }
#pragma unroll
            for (int ma = 0; ma < 2; ma++)
#pragma unroll
                for (int na = 0; na < 4; na++)
                    hmma(acc[ma][na], ah[ma],
                         bh[na >> 1][(na & 1) * 2], bh[na >> 1][(na & 1) * 2 + 1]);
        }
    }

    float* out = Cp + (long)blockIdx.x * 8192 * 128;
#pragma unroll
    for (int ma = 0; ma < 2; ma++) {
#pragma unroll
        for (int na = 0; na < 4; na++) {
            int c  = wn * 32 + na * 8 + (lane & 3) * 2;
            int r1 = row0 + wm * 32 + ma * 16 + (lane >> 2);
            int r2 = r1 + 8;
            *(float2*)&out[(long)r1 * 128 + c] =
                make_float2(acc[ma][na][0], acc[ma][na][1]);
            *(float2*)&out[(long)r2 * 128 + c] =
                make_float2(acc[ma][na][2], acc[ma][na][3]);
        }
    }
#undef H_LOAD
}

// ======================= fp32 -> fp16 cast ====================================
__global__ __launch_bounds__(256) void split16_kernel(
    const float4* __restrict__ in, uint2* __restrict__ out)
{
    int i = blockIdx.x * 256 + threadIdx.x;
    float4 v = in[i];
    __half2 h0 = __floats2half2_rn(v.x, v.y);
    __half2 h1 = __floats2half2_rn(v.z, v.w);
    uint2 o = {*(unsigned int*)&h0, *(unsigned int*)&h1};
    out[i] = o;
}

// ============== W [R,C] -> W^T fp16 [C,R] =====================================
__global__ __launch_bounds__(256) void tsplit16_kernel(
    const float* __restrict__ W, __half* __restrict__ T, int R, int C)
{
    __shared__ float t[32][33];
    int lane = threadIdx.x % 32;
    int ty = threadIdx.x / 32;
    int x = blockIdx.x * 32 + lane;
    int y0 = blockIdx.y * 32;
#pragma unroll
    for (int i = 0; i < 4; i++)
        t[ty + 8 * i][lane] = W[(long)(y0 + ty + 8 * i) * C + x];
    __syncthreads();
    int xo = y0 + lane;
    int yo = blockIdx.x * 32;
#pragma unroll
    for (int i = 0; i < 4; i++)
        T[(long)(yo + ty + 8 * i) * R + xo] = __float2half_rn(t[lane][ty + 8 * i]);
}

// ================= b12[n] = sum_j b1[j] W2[j,n] + b2[n] ======================
__global__ __launch_bounds__(256) void b12_kernel(
    const float* __restrict__ b1, const float* __restrict__ W2,
    const float* __restrict__ b2, float* __restrict__ b12)
{
    __shared__ float sm[256];
    int n = blockIdx.x;
    float s = 0.f;
    for (int j = threadIdx.x; j < 2048; j += 256)
        s = fmaf(b1[j], W2[(long)j * 128 + n], s);
    sm[threadIdx.x] = s;
    __syncthreads();
    for (int o = 128; o; o >>= 1) {
        if (threadIdx.x < o) sm[threadIdx.x] += sm[threadIdx.x + o];
        __syncthreads();
    }
    if (threadIdx.x == 0) b12[n] = sm[0] + b2[n];
}

// ====== fused: feat = p0 + p1 + b12; L2-normalize; emit fp32 + bf16 hi/lo =====
__global__ __launch_bounds__(256) void normalize_kernel(
    const float* __restrict__ p0, const float* __restrict__ p1,
    const float* __restrict__ b12, float* __restrict__ f,
    __nv_bfloat16* __restrict__ fhi, __nv_bfloat16* __restrict__ flo)
{
    int row  = blockIdx.x * 8 + (threadIdx.x >> 5);
    int lane = threadIdx.x & 31;
    int idx = row * 32 + lane;
    float4 a = ((const float4*)p0)[idx];
    float4 b = ((const float4*)p1)[idx];
    float4 bi = ((const float4*)b12)[lane];
    float4 v;
    v.x = a.x + b.x + bi.x;
    v.y = a.y + b.y + bi.y;
    v.z = a.z + b.z + bi.z;
    v.w = a.w + b.w + bi.w;
    float s = v.x * v.x + v.y * v.y + v.z * v.z + v.w * v.w;
#pragma unroll
    for (int o = 16; o; o >>= 1) s += __shfl_xor_sync(0xffffffffu, s, o);
    float r = rsqrtf(s);
    v.x *= r; v.y *= r; v.z *= r; v.w *= r;
    ((float4*)f)[idx] = v;
    float vv[4] = {v.x, v.y, v.z, v.w};
    __nv_bfloat16 h[4], l[4];
#pragma unroll
    for (int j = 0; j < 4; j++) {
        h[j] = __float2bfloat16(vv[j]);
        l[j] = __float2bfloat16(vv[j] - __bfloat162float(h[j]));
    }
    *(uint2*)&fhi[row * 128 + lane * 4] = *(uint2*)h;
    *(uint2*)&flo[row * 128 + lane * 4] = *(uint2*)l;
}

// ================= positive-pair similarity + zero S ==========================
__global__ __launch_bounds__(256) void pos_kernel(
    const float* __restrict__ f, float* __restrict__ pos, float* __restrict__ S)
{
    int row  = blockIdx.x * 8 + (threadIdx.x >> 5);
    int lane = threadIdx.x & 31;
    int partner = (row + 4096) & 8191;
    float4 a = ((const float4*)f)[row * 32 + lane];
    float4 b = ((const float4*)f)[partner * 32 + lane];
    float s = a.x * b.x + a.y * b.y + a.z * b.z + a.w * b.w;
#pragma unroll
    for (int o = 16; o; o >>= 1) s += __shfl_xor_sync(0xffffffffu, s, o);
    if (lane == 0) { pos[row] = s * TINV; S[row] = 0.f; }
}

// ============ tensorized sim + sum-of-exp (round-13 proven version) ==========
#define ROW2 272
#define LAR  (128 * ROW2)
#define LS_AH 0
#define LS_AL LAR
#define LS_BST (2 * LAR)
#define LS_RS  (6 * LAR)
#define LOSS_SMEM (6 * LAR + 1024)

__global__ __launch_bounds__(256) void loss_mma(
    const __nv_bfloat16* __restrict__ fhi, const __nv_bfloat16* __restrict__ flo,
    float* __restrict__ S)
{
    extern __shared__ char smem[];
    const unsigned int sb = smem_u32(smem);
    const int tid  = threadIdx.x;
    const int lane = tid & 31;
    const int wid  = tid >> 5;
    const int wm   = wid >> 1;
    const int wn   = wid & 1;
    const int r0   = blockIdx.y * 128;
    const int cbase = blockIdx.x * 4096;

    const int srow = tid >> 1;
    const int shal = tid & 1;
    const unsigned int sro = srow * ROW2 + shal * 128;

    {
        const __nv_bfloat16* gh = fhi + (long)(r0 + srow) * 128 + shal * 64;
        const __nv_bfloat16* gl = flo + (long)(r0 + srow) * 128 + shal * 64;
#pragma unroll
        for (int c = 0; c < 8; c++) {
            cp_async16(sb + LS_AH + sro + c * 16, gh + c * 8);
            cp_async16(sb + LS_AL + sro + c * 16, gl + c * 8);
        }
        cp_commit();
    }

#define LOAD_COL(s, ct) do { \
        unsigned int base = sb + LS_BST + (s) * (2 * LAR); \
        const __nv_bfloat16* gh = fhi + (long)(cbase + (ct) * 128 + srow) * 128 + shal * 64; \
        const __nv_bfloat16* gl = flo + (long)(cbase + (ct) * 128 + srow) * 128 + shal * 64; \
        _Pragma("unroll") \
        for (int c = 0; c < 8; c++) { \
            cp_async16(base + sro + c * 16, gh + c * 8); \
            cp_async16(base + LAR + sro + c * 16, gl + c * 8); \
        } \
        cp_commit(); \
    } while (0)

    LOAD_COL(0, 0);
    LOAD_COL(1, 1);

    float accS[4] = {0.f, 0.f, 0.f, 0.f};

    const unsigned int a_row  = lane & 15;
    const unsigned int a_koff = (lane >> 4) * 16;
    const unsigned int b_row  = (lane & 7) + ((lane >> 4) & 1) * 8;
    const unsigned int b_koff = ((lane >> 3) & 1) * 16;

    for (int ct = 0; ct < 32; ct++) {
        const unsigned int stg = sb + LS_BST + (ct & 1) * (2 * LAR);
        asm volatile("cp.async.wait_group 1;" ::: "memory");
        __syncthreads();

        float acc[2][8][4];
#pragma unroll
        for (int i = 0; i < 2; i++)
#pragma unroll
            for (int j = 0; j < 8; j++)
#pragma unroll
                for (int q = 0; q < 4; q++) acc[i][j][q] = 0.f;

#pragma unroll
        for (int s = 0; s < 8; s++) {
            const unsigned int kb = s * 32;
            unsigned int ah[2][4], al[2][4];
#pragma unroll
            for (int ma = 0; ma < 2; ma++) {
                unsigned int roff = (wm * 32 + ma * 16 + a_row) * ROW2 + kb + a_koff;
                ldmat4(ah[ma], sb + LS_AH + roff);
                ldmat4(al[ma], sb + LS_AL + roff);
            }
            unsigned int bh[4][4], bl[4][4];
#pragma unroll
            for (int nb = 0; nb < 4; nb++) {
                unsigned int roff = (wn * 64 + nb * 16 + b_row) * ROW2 + kb + b_koff;
                ldmat4(bh[nb], stg + roff);
                ldmat4(bl[nb], stg + LAR + roff);
            }
#pragma unroll
            for (int ma = 0; ma < 2; ma++)
#pragma unroll
                for (int na = 0; na < 8; na++) {
                    unsigned int h0 = bh[na >> 1][(na & 1) * 2];
                    unsigned int h1 = bh[na >> 1][(na & 1) * 2 + 1];
                    unsigned int l0 = bl[na >> 1][(na & 1) * 2];
                    unsigned int l1 = bl[na >> 1][(na & 1) * 2 + 1];
                    bmma(acc[ma][na], ah[ma], h0, h1);
                    bmma(acc[ma][na], ah[ma], l0, l1);
                    bmma(acc[ma][na], al[ma], h0, h1);
                }
        }

        const int c0 = cbase + ct * 128;
#pragma unroll
        for (int ma = 0; ma < 2; ma++) {
            int gi1 = r0 + wm * 32 + ma * 16 + (lane >> 2);
            int gi2 = gi1 + 8;
#pragma unroll
            for (int na = 0; na < 8; na++) {
                int gj = c0 + wn * 64 + na * 8 + (lane & 3) * 2;
                float e0 = exp2f(fmaf(acc[ma][na][0], K1E, -K1E));
                float e1 = exp2f(fmaf(acc[ma][na][1], K1E, -K1E));
                float e2 = exp2f(fmaf(acc[ma][na][2], K1E, -K1E));
                float e3 = exp2f(fmaf(acc[ma][na][3], K1E, -K1E));
                accS[ma * 2 + 0] += ((gi1 != gj)     ? e0 : 0.f)
                                  + ((gi1 != gj + 1) ? e1 : 0.f);
                accS[ma * 2 + 1] += ((gi2 != gj)     ? e2 : 0.f)
                                  + ((gi2 != gj + 1) ? e3 : 0.f);
            }
        }

        __syncthreads();
        if (ct + 2 < 32) LOAD_COL(ct & 1, ct + 2);
        else cp_commit();
    }

#pragma unroll
    for (int i = 0; i < 4; i++) {
        accS[i] += __shfl_xor_sync(0xffffffffu, accS[i], 1);
        accS[i] += __shfl_xor_sync(0xffffffffu, accS[i], 2);
    }
    __syncthreads();
    float* rs = (float*)(smem + LS_RS);
    if ((lane & 3) == 0) {
#pragma unroll
        for (int i = 0; i < 4; i++) {
            int rloc = wm * 32 + (i >> 1) * 16 + (i & 1) * 8 + (lane >> 2);
            rs[rloc * 2 + wn] = accS[i];
        }
    }
    __syncthreads();
    if (tid < 128)
        atomicAdd(&S[r0 + tid], rs[tid * 2] + rs[tid * 2 + 1]);
#undef LOAD_COL
}

// ================= final deterministic reduction ==============================
__global__ __launch_bounds__(256) void final_kernel(
    const float* __restrict__ S, const float* __restrict__ pos,
    float* __restrict__ out)
{
    __shared__ float sm[256];
    float v = 0.f;
    for (int i = threadIdx.x; i < 8192; i += 256)
        v += TINV + logf(S[i]) - pos[i];
    sm[threadIdx.x] = v;
    __syncthreads();
    for (int o = 128; o; o >>= 1) {
        if (threadIdx.x < o) sm[threadIdx.x] += sm[threadIdx.x + o];
        __syncthreads();
    }
    if (threadIdx.x == 0) out[0] = sm[0] * (1.0f / 8192.0f);
}

// ================= launch =====================================================
extern "C" void kernel_launch(void* const* d_in, const int* in_sizes, int n_in,
                              void* d_out, int out_size)
{
    const float* x1 = (const float*)d_in[0];
    const float* x2 = (const float*)d_in[1];
    const float* W0 = (const float*)d_in[2];
    const float* b0 = (const float*)d_in[3];
    const float* W1 = (const float*)d_in[4];
    const float* b1 = (const float*)d_in[5];
    const float* W2 = (const float*)d_in[6];
    const float* b2 = (const float*)d_in[7];
    float* out = (float*)d_out;

    __half *x16, *w0t, *w1e, *w2t, *w12, *a0;
    __nv_bfloat16 *fhi, *flo;
    float *feat, *pos, *S, *b12, *w12p, *featp;
    cudaGetSymbolAddress((void**)&x16, g_x16);
    cudaGetSymbolAddress((void**)&w0t, g_w0t);
    cudaGetSymbolAddress((void**)&w1e, g_w1e);
    cudaGetSymbolAddress((void**)&w2t, g_w2t);
    cudaGetSymbolAddress((void**)&w12, g_w12);
    cudaGetSymbolAddress((void**)&w12p, g_w12p);
    cudaGetSymbolAddress((void**)&a0, g_a0);
    cudaGetSymbolAddress((void**)&featp, g_featp);
    cudaGetSymbolAddress((void**)&fhi, g_fhi);
    cudaGetSymbolAddress((void**)&flo, g_flo);
    cudaGetSymbolAddress((void**)&feat, g_feat);
    cudaGetSymbolAddress((void**)&pos, g_pos);
    cudaGetSymbolAddress((void**)&S, g_S);
    cudaGetSymbolAddress((void**)&b12, g_b12);

    cudaFuncSetAttribute(gemm_f16<true>,
                         cudaFuncAttributeMaxDynamicSharedMemorySize, GEMM_SMEM);
    cudaFuncSetAttribute(gemm_w12,
                         cudaFuncAttributeMaxDynamicSharedMemorySize, W12_SMEM);
    cudaFuncSetAttribute(gemm_head,
                         cudaFuncAttributeMaxDynamicSharedMemorySize, HEAD_SMEM);
    cudaFuncSetAttribute(loss_mma,
                         cudaFuncAttributeMaxDynamicSharedMemorySize, LOSS_SMEM);

    // ---- weight prep (fp16) ----
    tsplit16_kernel<<<dim3(64, 64), 256>>>(W0, w0t, 2048, 2048);
    tsplit16_kernel<<<dim3(4, 64), 256>>>(W2, w2t, 2048, 128);
    split16_kernel<<<(2048 * 2048 / 4) / 256, 256>>>(
        (const float4*)W1, (uint2*)w1e);

    gemm_w12<<<dim3(8, 16), 256, W12_SMEM>>>(w2t, w1e, w12p);
    w12_reduce<<<(128 * 2048 / 4) / 256, 256>>>(w12p, w12);
    b12_kernel<<<128, 256>>>(b1, W2, b2, b12);

    // ---- input cast (both views -> M=8192 fp16) ----
    const int NSPLIT = (4096 * 2048 / 4) / 256;
    split16_kernel<<<NSPLIT, 256>>>((const float4*)x1, (uint2*)x16);
    split16_kernel<<<NSPLIT, 256>>>((const float4*)x2,
                                    (uint2*)(x16 + (long)4096 * 2048));

    // ---- collapsed MLP ----
    gemm_f16<true><<<dim3(64, 16), 256, GEMM_SMEM>>>(x16, w0t, b0, a0);
    gemm_head<<<dim3(2, 128), 256, HEAD_SMEM>>>(a0, w12, featp);

    normalize_kernel<<<1024, 256>>>(featp, featp + (long)8192 * 128, b12,
                                    feat, fhi, flo);
    pos_kernel<<<1024, 256>>>(feat, pos, S);
    loss_mma<<<dim3(2, 64), 256, LOSS_SMEM>>>(fhi, flo, S);
    final_kernel<<<1, 256>>>(S, pos, out);
}

// round 16
// speedup vs baseline: 1.0696x; 1.0696x over previous
#include <cuda_runtime.h>
#include <cuda_fp16.h>
#include <cuda_bf16.h>
#include <stdint.h>
#include <math.h>

#define TINV 14.2857142857142857f   /* 1 / 0.07 */
#define K1E  20.6099291083577f      /* TINV * log2(e) */

// -------- scratch (no allocations allowed) --------
static __device__ __half g_x16[8192 * 2048];
static __device__ __half g_w0t[2048 * 2048];
static __device__ __half g_w1e[2048 * 2048];
static __device__ __half g_w2t[128 * 2048];
static __device__ __half g_w12[128 * 2048];
static __device__ float  g_w12p[8 * 128 * 2048];
static __device__ __half g_a0[8192 * 2048];
static __device__ float  g_featp[2 * 8192 * 128];
static __device__ float  g_b12[128];
static __device__ float  g_feat[8192 * 128];
static __device__ __nv_bfloat16 g_fhi[8192 * 128];
static __device__ __nv_bfloat16 g_flo[8192 * 128];
static __device__ float g_pos[8192];
static __device__ float g_S[8192];

// ======================= PTX helpers (baseline ISA only) =====================
__device__ __forceinline__ void cp_async16(unsigned int saddr, const void* gptr) {
    asm volatile("cp.async.ca.shared.global [%0], [%1], 16;" :: "r"(saddr), "l"(gptr));
}
__device__ __forceinline__ void cp_commit() {
    asm volatile("cp.async.commit_group;");
}
__device__ __forceinline__ unsigned int smem_u32(const void* p) {
    unsigned int a;
    asm("{ .reg .u64 t; cvta.to.shared.u64 t, %1; cvt.u32.u64 %0, t; }" : "=r"(a) : "l"(p));
    return a;
}
__device__ __forceinline__ void ldmat4(unsigned int* r, unsigned int addr) {
    asm volatile("ldmatrix.sync.aligned.m8n8.x4.shared.b16 {%0,%1,%2,%3}, [%4];"
        : "=r"(r[0]), "=r"(r[1]), "=r"(r[2]), "=r"(r[3]) : "r"(addr));
}
__device__ __forceinline__ void hmma(float* d, const unsigned int* a,
                                     unsigned int b0, unsigned int b1) {
    asm volatile(
        "mma.sync.aligned.m16n8k16.row.col.f32.f16.f16.f32 "
        "{%0,%1,%2,%3}, {%4,%5,%6,%7}, {%8,%9}, {%0,%1,%2,%3};"
        : "+f"(d[0]), "+f"(d[1]), "+f"(d[2]), "+f"(d[3])
        : "r"(a[0]), "r"(a[1]), "r"(a[2]), "r"(a[3]), "r"(b0), "r"(b1));
}
__device__ __forceinline__ void bmma(float* d, const unsigned int* a,
                                     unsigned int b0, unsigned int b1) {
    asm volatile(
        "mma.sync.aligned.m16n8k16.row.col.f32.bf16.bf16.f32 "
        "{%0,%1,%2,%3}, {%4,%5,%6,%7}, {%8,%9}, {%0,%1,%2,%3};"
        : "+f"(d[0]), "+f"(d[1]), "+f"(d[2]), "+f"(d[3])
        : "r"(a[0]), "r"(a[1]), "r"(a[2]), "r"(a[3]), "r"(b0), "r"(b1));
}

// ======================= fp16 warp-MMA GEMM (128x128) ========================
// 4-stage cp.async ring + wait_group 2, ONE barrier per chunk, 2 CTAs/SM.
#define ROWB 80
#define F_A 0
#define F_B (128 * ROWB)            /* 10240 */
#define FSTAGE (2 * 128 * ROWB)     /* 20480 */
#define SMEM_BIAS 0
#define SMEM_STAGE0 1024
#define GEMM_SMEM (SMEM_STAGE0 + 4 * FSTAGE)   /* 82944 */

template <bool RELU>
__global__ __launch_bounds__(256, 2) void gemm_f16(
    const __half* __restrict__ A, const __half* __restrict__ B,
    const float* __restrict__ bias, __half* __restrict__ C)
{
    extern __shared__ char smem[];
    const unsigned int sb = smem_u32(smem);
    const int tid  = threadIdx.x;
    const int lane = tid & 31;
    const int wid  = tid >> 5;
    const int wm   = wid >> 1;
    const int wn   = wid & 1;
    const int row0 = blockIdx.x * 128;
    const int col0 = blockIdx.y * 128;
    const int K = 2048;
    const int NKT = 64;

    if (tid < 128) ((float*)(smem + SMEM_BIAS))[tid] = bias[col0 + tid];

    const int srow = tid >> 1;
    const int shal = tid & 1;
    const __half* gA = A + (long)(row0 + srow) * K + shal * 16;
    const __half* gB = B + (long)(col0 + srow) * K + shal * 16;
    const unsigned int sro = srow * ROWB + shal * 32;

#define LOAD_STAGE(stg, k0) do { \
        cp_async16((stg) + F_A + sro,      gA + (k0)); \
        cp_async16((stg) + F_A + sro + 16, gA + (k0) + 8); \
        cp_async16((stg) + F_B + sro,      gB + (k0)); \
        cp_async16((stg) + F_B + sro + 16, gB + (k0) + 8); \
    } while (0)

#pragma unroll
    for (int b = 0; b < 3; b++) {
        LOAD_STAGE(sb + SMEM_STAGE0 + b * FSTAGE, b * 32);
        cp_commit();
    }

    float acc[2][8][4];
#pragma unroll
    for (int i = 0; i < 2; i++)
#pragma unroll
        for (int j = 0; j < 8; j++)
#pragma unroll
            for (int q = 0; q < 4; q++) acc[i][j][q] = 0.f;

    const unsigned int a_row  = lane & 15;
    const unsigned int a_koff = (lane >> 4) * 16;
    const unsigned int b_row  = (lane & 7) + ((lane >> 4) & 1) * 8;
    const unsigned int b_koff = ((lane >> 3) & 1) * 16;

    for (int kt = 0; kt < NKT; kt++) {
        const unsigned int stg = sb + SMEM_STAGE0 + (kt & 3) * FSTAGE;
        asm volatile("cp.async.wait_group 2;" ::: "memory");
        __syncthreads();

        if (kt + 3 < NKT) {
            const unsigned int pst = sb + SMEM_STAGE0 + ((kt + 3) & 3) * FSTAGE;
            LOAD_STAGE(pst, (kt + 3) * 32);
        }
        cp_commit();

#pragma unroll
        for (int s = 0; s < 2; s++) {
            const unsigned int kb = s * 32;
            unsigned int ah[2][4];
#pragma unroll
            for (int ma = 0; ma < 2; ma++) {
                unsigned int roff = (wm * 32 + ma * 16 + a_row) * ROWB + kb + a_koff;
                ldmat4(ah[ma], stg + F_A + roff);
            }
            unsigned int bh[4][4];
#pragma unroll
            for (int nb = 0; nb < 4; nb++) {
                unsigned int roff = (wn * 64 + nb * 16 + b_row) * ROWB + kb + b_koff;
                ldmat4(bh[nb], stg + F_B + roff);
            }
#pragma unroll
            for (int ma = 0; ma < 2; ma++)
#pragma unroll
                for (int na = 0; na < 8; na++)
                    hmma(acc[ma][na], ah[ma],
                         bh[na >> 1][(na & 1) * 2], bh[na >> 1][(na & 1) * 2 + 1]);
        }
    }

    const float* bs = (const float*)(smem + SMEM_BIAS);
    const int ccol = wn * 64;
#pragma unroll
    for (int ma = 0; ma < 2; ma++) {
#pragma unroll
        for (int na = 0; na < 8; na++) {
            int c  = ccol + na * 8 + (lane & 3) * 2;
            int r1 = row0 + wm * 32 + ma * 16 + (lane >> 2);
            int r2 = r1 + 8;
            float v0 = acc[ma][na][0] + bs[c];
            float v1 = acc[ma][na][1] + bs[c + 1];
            float v2 = acc[ma][na][2] + bs[c];
            float v3 = acc[ma][na][3] + bs[c + 1];
            if (RELU) {
                v0 = fmaxf(v0, 0.f); v1 = fmaxf(v1, 0.f);
                v2 = fmaxf(v2, 0.f); v3 = fmaxf(v3, 0.f);
            }
            *(__half2*)&C[(long)r1 * 2048 + col0 + c] = __floats2half2_rn(v0, v1);
            *(__half2*)&C[(long)r2 * 2048 + col0 + c] = __floats2half2_rn(v2, v3);
        }
    }
#undef LOAD_STAGE
}

// ======================= W12 split-K fp16 GEMM: grid (8, 16) =================
__global__ __launch_bounds__(256, 2) void gemm_w12(
    const __half* __restrict__ A, const __half* __restrict__ B,
    float* __restrict__ Cp)
{
    extern __shared__ char smem[];
    const unsigned int sb = smem_u32(smem);
    const int tid  = threadIdx.x;
    const int lane = tid & 31;
    const int wid  = tid >> 5;
    const int wm   = wid >> 1;
    const int wn   = wid & 1;
    const int col0 = blockIdx.y * 128;
    const int kbase = blockIdx.x * 256;
    const int K = 2048;
    const int NKT = 8;

    const int srow = tid >> 1;
    const int shal = tid & 1;
    const __half* gA = A + (long)srow * K + kbase + shal * 16;
    const __half* gB = B + (long)(col0 + srow) * K + kbase + shal * 16;
    const unsigned int sro = srow * ROWB + shal * 32;

#define LOAD_STAGE(stg, k0) do { \
        cp_async16((stg) + F_A + sro,      gA + (k0)); \
        cp_async16((stg) + F_A + sro + 16, gA + (k0) + 8); \
        cp_async16((stg) + F_B + sro,      gB + (k0)); \
        cp_async16((stg) + F_B + sro + 16, gB + (k0) + 8); \
    } while (0)

#pragma unroll
    for (int b = 0; b < 3; b++) {
        LOAD_STAGE(sb + SMEM_STAGE0 + b * FSTAGE, b * 32);
        cp_commit();
    }

    float acc[2][8][4];
#pragma unroll
    for (int i = 0; i < 2; i++)
#pragma unroll
        for (int j = 0; j < 8; j++)
#pragma unroll
            for (int q = 0; q < 4; q++) acc[i][j][q] = 0.f;

    const unsigned int a_row  = lane & 15;
    const unsigned int a_koff = (lane >> 4) * 16;
    const unsigned int b_row  = (lane & 7) + ((lane >> 4) & 1) * 8;
    const unsigned int b_koff = ((lane >> 3) & 1) * 16;

    for (int kt = 0; kt < NKT; kt++) {
        const unsigned int stg = sb + SMEM_STAGE0 + (kt & 3) * FSTAGE;
        asm volatile("cp.async.wait_group 2;" ::: "memory");
        __syncthreads();

        if (kt + 3 < NKT) {
            const unsigned int pst = sb + SMEM_STAGE0 + ((kt + 3) & 3) * FSTAGE;
            LOAD_STAGE(pst, (kt + 3) * 32);
        }
        cp_commit();

#pragma unroll
        for (int s = 0; s < 2; s++) {
            const unsigned int kb = s * 32;
            unsigned int ah[2][4];
#pragma unroll
            for (int ma = 0; ma < 2; ma++) {
                unsigned int roff = (wm * 32 + ma * 16 + a_row) * ROWB + kb + a_koff;
                ldmat4(ah[ma], stg + F_A + roff);
            }
            unsigned int bh[4][4];
#pragma unroll
            for (int nb = 0; nb < 4; nb++) {
                unsigned int roff = (wn * 64 + nb * 16 + b_row) * ROWB + kb + b_koff;
                ldmat4(bh[nb], stg + F_B + roff);
            }
#pragma unroll
            for (int ma = 0; ma < 2; ma++)
#pragma unroll
                for (int na = 0; na < 8; na++)
                    hmma(acc[ma][na], ah[ma],
                         bh[na >> 1][(na & 1) * 2], bh[na >> 1][(na & 1) * 2 + 1]);
        }
    }

    float* out = Cp + (long)blockIdx.x * 128 * 2048;
#pragma unroll
    for (int ma = 0; ma < 2; ma++) {
#pragma unroll
        for (int na = 0; na < 8; na++) {
            int c  = col0 + wn * 64 + na * 8 + (lane & 3) * 2;
            int r1 = wm * 32 + ma * 16 + (lane >> 2);
            int r2 = r1 + 8;
            *(float2*)&out[(long)r1 * 2048 + c] =
                make_float2(acc[ma][na][0], acc[ma][na][1]);
            *(float2*)&out[(long)r2 * 2048 + c] =
                make_float2(acc[ma][na][2], acc[ma][na][3]);
        }
    }
#undef LOAD_STAGE
}

// =========== fixed-order reduce of 8 W12 slices -> fp16 ======================
__global__ __launch_bounds__(256) void w12_reduce(
    const float* __restrict__ Cp, __half* __restrict__ T)
{
    int i = blockIdx.x * 256 + threadIdx.x;
    float4 s = ((const float4*)Cp)[i];
#pragma unroll
    for (int k = 1; k < 8; k++) {
        float4 p = ((const float4*)(Cp + (long)k * 128 * 2048))[i];
        s.x += p.x; s.y += p.y; s.z += p.z; s.w += p.w;
    }
    __half2 h0 = __floats2half2_rn(s.x, s.y);
    __half2 h1 = __floats2half2_rn(s.z, s.w);
    uint2 o = {*(unsigned int*)&h0, *(unsigned int*)&h1};
    ((uint2*)T)[i] = o;
}

// =================== head GEMM fp16 split-K: grid (2, 128), 4 stages =========
#define H_A 0
#define H_B (64 * ROWB)
#define H_STAGE (H_B + 128 * ROWB)
#define HEAD_SMEM (1024 + 4 * H_STAGE)

__global__ __launch_bounds__(256, 2) void gemm_head(
    const __half* __restrict__ A, const __half* __restrict__ B,
    float* __restrict__ Cp)
{
    extern __shared__ char smem[];
    const unsigned int sb = smem_u32(smem);
    const int tid  = threadIdx.x;
    const int lane = tid & 31;
    const int wid  = tid >> 5;
    const int wm   = wid >> 2;
    const int wn   = wid & 3;
    const int row0 = blockIdx.y * 64;
    const int kbase = blockIdx.x * 1024;
    const int K = 2048;
    const int NKT = 32;

    const int sar = tid >> 2;
    const int saq = tid & 3;
    const __half* gA = A + (long)(row0 + sar) * K + kbase + saq * 8;
    const unsigned int sra = sar * ROWB + saq * 16;
    const int sbr = tid >> 1;
    const int sbh = tid & 1;
    const __half* gB = B + (long)sbr * K + kbase + sbh * 16;
    const unsigned int srb = sbr * ROWB + sbh * 32;

#define H_LOAD(stg, k0) do { \
        cp_async16((stg) + H_A + sra, gA + (k0)); \
        cp_async16((stg) + H_B + srb,      gB + (k0)); \
        cp_async16((stg) + H_B + srb + 16, gB + (k0) + 8); \
    } while (0)

#pragma unroll
    for (int b = 0; b < 3; b++) {
        H_LOAD(sb + SMEM_STAGE0 + b * H_STAGE, b * 32);
        cp_commit();
    }

    float acc[2][4][4];
#pragma unroll
    for (int i = 0; i < 2; i++)
#pragma unroll
        for (int j = 0; j < 4; j++)
#pragma unroll
            for (int q = 0; q < 4; q++) acc[i][j][q] = 0.f;

    const unsigned int a_row  = lane & 15;
    const unsigned int a_koff = (lane >> 4) * 16;
    const unsigned int b_row  = (lane & 7) + ((lane >> 4) & 1) * 8;
    const unsigned int b_koff = ((lane >> 3) & 1) * 16;

    for (int kt = 0; kt < NKT; kt++) {
        const unsigned int stg = sb + SMEM_STAGE0 + (kt & 3) * H_STAGE;
        asm volatile("cp.async.wait_group 2;" ::: "memory");
        __syncthreads();

        if (kt + 3 < NKT) {
            const unsigned int pst = sb + SMEM_STAGE0 + ((kt + 3) & 3) * H_STAGE;
            H_LOAD(pst, (kt + 3) * 32);
        }
        cp_commit();

#pragma unroll
        for (int s = 0; s < 2; s++) {
            const unsigned int kb = s * 32;
            unsigned int ah[2][4];
#pragma unroll
            for (int ma = 0; ma < 2; ma++) {
                unsigned int roff = (wm * 32 + ma * 16 + a_row) * ROWB + kb + a_koff;
                ldmat4(ah[ma], stg + H_A + roff);
            }
            unsigned int bh[2][4];
#pragma unroll
            for (int nb = 0; nb < 2; nb++) {
                unsigned int roff = (wn * 32 + nb * 16 + b_row) * ROWB + kb + b_koff;
                ldmat4(bh[nb], stg + H_B + roff);
            }
#pragma unroll
            for (int ma = 0; ma < 2; ma++)
#pragma unroll
                for (int na = 0; na < 4; na++)
                    hmma(acc[ma][na], ah[ma],
                         bh[na >> 1][(na & 1) * 2], bh[na >> 1][(na & 1) * 2 + 1]);
        }
    }

    float* out = Cp + (long)blockIdx.x * 8192 * 128;
#pragma unroll
    for (int ma = 0; ma < 2; ma++) {
#pragma unroll
        for (int na = 0; na < 4; na++) {
            int c  = wn * 32 + na * 8 + (lane & 3) * 2;
            int r1 = row0 + wm * 32 + ma * 16 + (lane >> 2);
            int r2 = r1 + 8;
            *(float2*)&out[(long)r1 * 128 + c] =
                make_float2(acc[ma][na][0], acc[ma][na][1]);
            *(float2*)&out[(long)r2 * 128 + c] =
                make_float2(acc[ma][na][2], acc[ma][na][3]);
        }
    }
#undef H_LOAD
}

// ======================= fp32 -> fp16 cast ====================================
__global__ __launch_bounds__(256) void split16_kernel(
    const float4* __restrict__ in, uint2* __restrict__ out)
{
    int i = blockIdx.x * 256 + threadIdx.x;
    float4 v = in[i];
    __half2 h0 = __floats2half2_rn(v.x, v.y);
    __half2 h1 = __floats2half2_rn(v.z, v.w);
    uint2 o = {*(unsigned int*)&h0, *(unsigned int*)&h1};
    out[i] = o;
}

// ============== W [R,C] -> W^T fp16 [C,R] =====================================
__global__ __launch_bounds__(256) void tsplit16_kernel(
    const float* __restrict__ W, __half* __restrict__ T, int R, int C)
{
    __shared__ float t[32][33];
    int lane = threadIdx.x % 32;
    int ty = threadIdx.x / 32;
    int x = blockIdx.x * 32 + lane;
    int y0 = blockIdx.y * 32;
#pragma unroll
    for (int i = 0; i < 4; i++)
        t[ty + 8 * i][lane] = W[(long)(y0 + ty + 8 * i) * C + x];
    __syncthreads();
    int xo = y0 + lane;
    int yo = blockIdx.x * 32;
#pragma unroll
    for (int i = 0; i < 4; i++)
        T[(long)(yo + ty + 8 * i) * R + xo] = __float2half_rn(t[lane][ty + 8 * i]);
}

// ================= b12[n] = sum_j b1[j] W2[j,n] + b2[n] ======================
__global__ __launch_bounds__(256) void b12_kernel(
    const float* __restrict__ b1, const float* __restrict__ W2,
    const float* __restrict__ b2, float* __restrict__ b12)
{
    __shared__ float sm[256];
    int n = blockIdx.x;
    float s = 0.f;
    for (int j = threadIdx.x; j < 2048; j += 256)
        s = fmaf(b1[j], W2[(long)j * 128 + n], s);
    sm[threadIdx.x] = s;
    __syncthreads();
    for (int o = 128; o; o >>= 1) {
        if (threadIdx.x < o) sm[threadIdx.x] += sm[threadIdx.x + o];
        __syncthreads();
    }
    if (threadIdx.x == 0) b12[n] = sm[0] + b2[n];
}

// ====== fused: feat = p0 + p1 + b12; L2-normalize; emit fp32 + bf16 hi/lo =====
__global__ __launch_bounds__(256) void normalize_kernel(
    const float* __restrict__ p0, const float* __restrict__ p1,
    const float* __restrict__ b12, float* __restrict__ f,
    __nv_bfloat16* __restrict__ fhi, __nv_bfloat16* __restrict__ flo)
{
    int row  = blockIdx.x * 8 + (threadIdx.x >> 5);
    int lane = threadIdx.x & 31;
    int idx = row * 32 + lane;
    float4 a = ((const float4*)p0)[idx];
    float4 b = ((const float4*)p1)[idx];
    float4 bi = ((const float4*)b12)[lane];
    float4 v;
    v.x = a.x + b.x + bi.x;
    v.y = a.y + b.y + bi.y;
    v.z = a.z + b.z + bi.z;
    v.w = a.w + b.w + bi.w;
    float s = v.x * v.x + v.y * v.y + v.z * v.z + v.w * v.w;
#pragma unroll
    for (int o = 16; o; o >>= 1) s += __shfl_xor_sync(0xffffffffu, s, o);
    float r = rsqrtf(s);
    v.x *= r; v.y *= r; v.z *= r; v.w *= r;
    ((float4*)f)[idx] = v;
    float vv[4] = {v.x, v.y, v.z, v.w};
    __nv_bfloat16 h[4], l[4];
#pragma unroll
    for (int j = 0; j < 4; j++) {
        h[j] = __float2bfloat16(vv[j]);
        l[j] = __float2bfloat16(vv[j] - __bfloat162float(h[j]));
    }
    *(uint2*)&fhi[row * 128 + lane * 4] = *(uint2*)h;
    *(uint2*)&flo[row * 128 + lane * 4] = *(uint2*)l;
}

// ================= positive-pair similarity + zero S ==========================
__global__ __launch_bounds__(256) void pos_kernel(
    const float* __restrict__ f, float* __restrict__ pos, float* __restrict__ S)
{
    int row  = blockIdx.x * 8 + (threadIdx.x >> 5);
    int lane = threadIdx.x & 31;
    int partner = (row + 4096) & 8191;
    float4 a = ((const float4*)f)[row * 32 + lane];
    float4 b = ((const float4*)f)[partner * 32 + lane];
    float s = a.x * b.x + a.y * b.y + a.z * b.z + a.w * b.w;
#pragma unroll
    for (int o = 16; o; o >>= 1) s += __shfl_xor_sync(0xffffffffu, s, o);
    if (lane == 0) { pos[row] = s * TINV; S[row] = 0.f; }
}

// ============ tensorized sim + sum-of-exp (round-13 proven version) ==========
#define ROW2 272
#define LAR  (128 * ROW2)
#define LS_AH 0
#define LS_AL LAR
#define LS_BST (2 * LAR)
#define LS_RS  (6 * LAR)
#define LOSS_SMEM (6 * LAR + 1024)

__global__ __launch_bounds__(256) void loss_mma(
    const __nv_bfloat16* __restrict__ fhi, const __nv_bfloat16* __restrict__ flo,
    float* __restrict__ S)
{
    extern __shared__ char smem[];
    const unsigned int sb = smem_u32(smem);
    const int tid  = threadIdx.x;
    const int lane = tid & 31;
    const int wid  = tid >> 5;
    const int wm   = wid >> 1;
    const int wn   = wid & 1;
    const int r0   = blockIdx.y * 128;
    const int cbase = blockIdx.x * 4096;

    const int srow = tid >> 1;
    const int shal = tid & 1;
    const unsigned int sro = srow * ROW2 + shal * 128;

    {
        const __nv_bfloat16* gh = fhi + (long)(r0 + srow) * 128 + shal * 64;
        const __nv_bfloat16* gl = flo + (long)(r0 + srow) * 128 + shal * 64;
#pragma unroll
        for (int c = 0; c < 8; c++) {
            cp_async16(sb + LS_AH + sro + c * 16, gh + c * 8);
            cp_async16(sb + LS_AL + sro + c * 16, gl + c * 8);
        }
        cp_commit();
    }

#define LOAD_COL(s, ct) do { \
        unsigned int base = sb + LS_BST + (s) * (2 * LAR); \
        const __nv_bfloat16* gh = fhi + (long)(cbase + (ct) * 128 + srow) * 128 + shal * 64; \
        const __nv_bfloat16* gl = flo + (long)(cbase + (ct) * 128 + srow) * 128 + shal * 64; \
        _Pragma("unroll") \
        for (int c = 0; c < 8; c++) { \
            cp_async16(base + sro + c * 16, gh + c * 8); \
            cp_async16(base + LAR + sro + c * 16, gl + c * 8); \
        } \
        cp_commit(); \
    } while (0)

    LOAD_COL(0, 0);
    LOAD_COL(1, 1);

    float accS[4] = {0.f, 0.f, 0.f, 0.f};

    const unsigned int a_row  = lane & 15;
    const unsigned int a_koff = (lane >> 4) * 16;
    const unsigned int b_row  = (lane & 7) + ((lane >> 4) & 1) * 8;
    const unsigned int b_koff = ((lane >> 3) & 1) * 16;

    for (int ct = 0; ct < 32; ct++) {
        const unsigned int stg = sb + LS_BST + (ct & 1) * (2 * LAR);
        asm volatile("cp.async.wait_group 1;" ::: "memory");
        __syncthreads();

        float acc[2][8][4];
#pragma unroll
        for (int i = 0; i < 2; i++)
#pragma unroll
            for (int j = 0; j < 8; j++)
#pragma unroll
                for (int q = 0; q < 4; q++) acc[i][j][q] = 0.f;

#pragma unroll
        for (int s = 0; s < 8; s++) {
            const unsigned int kb = s * 32;
            unsigned int ah[2][4], al[2][4];
#pragma unroll
            for (int ma = 0; ma < 2; ma++) {
                unsigned int roff = (wm * 32 + ma * 16 + a_row) * ROW2 + kb + a_koff;
                ldmat4(ah[ma], sb + LS_AH + roff);
                ldmat4(al[ma], sb + LS_AL + roff);
            }
            unsigned int bh[4][4], bl[4][4];
#pragma unroll
            for (int nb = 0; nb < 4; nb++) {
                unsigned int roff = (wn * 64 + nb * 16 + b_row) * ROW2 + kb + b_koff;
                ldmat4(bh[nb], stg + roff);
                ldmat4(bl[nb], stg + LAR + roff);
            }
#pragma unroll
            for (int ma = 0; ma < 2; ma++)
#pragma unroll
                for (int na = 0; na < 8; na++) {
                    unsigned int h0 = bh[na >> 1][(na & 1) * 2];
                    unsigned int h1 = bh[na >> 1][(na & 1) * 2 + 1];
                    unsigned int l0 = bl[na >> 1][(na & 1) * 2];
                    unsigned int l1 = bl[na >> 1][(na & 1) * 2 + 1];
                    bmma(acc[ma][na], ah[ma], h0, h1);
                    bmma(acc[ma][na], ah[ma], l0, l1);
                    bmma(acc[ma][na], al[ma], h0, h1);
                }
        }

        const int c0 = cbase + ct * 128;
#pragma unroll
        for (int ma = 0; ma < 2; ma++) {
            int gi1 = r0 + wm * 32 + ma * 16 + (lane >> 2);
            int gi2 = gi1 + 8;
#pragma unroll
            for (int na = 0; na < 8; na++) {
                int gj = c0 + wn * 64 + na * 8 + (lane & 3) * 2;
                float e0 = exp2f(fmaf(acc[ma][na][0], K1E, -K1E));
                float e1 = exp2f(fmaf(acc[ma][na][1], K1E, -K1E));
                float e2 = exp2f(fmaf(acc[ma][na][2], K1E, -K1E));
                float e3 = exp2f(fmaf(acc[ma][na][3], K1E, -K1E));
                accS[ma * 2 + 0] += ((gi1 != gj)     ? e0 : 0.f)
                                  + ((gi1 != gj + 1) ? e1 : 0.f);
                accS[ma * 2 + 1] += ((gi2 != gj)     ? e2 : 0.f)
                                  + ((gi2 != gj + 1) ? e3 : 0.f);
            }
        }

        __syncthreads();
        if (ct + 2 < 32) LOAD_COL(ct & 1, ct + 2);
        else cp_commit();
    }

#pragma unroll
    for (int i = 0; i < 4; i++) {
        accS[i] += __shfl_xor_sync(0xffffffffu, accS[i], 1);
        accS[i] += __shfl_xor_sync(0xffffffffu, accS[i], 2);
    }
    __syncthreads();
    float* rs = (float*)(smem + LS_RS);
    if ((lane & 3) == 0) {
#pragma unroll
        for (int i = 0; i < 4; i++) {
            int rloc = wm * 32 + (i >> 1) * 16 + (i & 1) * 8 + (lane >> 2);
            rs[rloc * 2 + wn] = accS[i];
        }
    }
    __syncthreads();
    if (tid < 128)
        atomicAdd(&S[r0 + tid], rs[tid * 2] + rs[tid * 2 + 1]);
#undef LOAD_COL
}

// ================= final deterministic reduction ==============================
__global__ __launch_bounds__(256) void final_kernel(
    const float* __restrict__ S, const float* __restrict__ pos,
    float* __restrict__ out)
{
    __shared__ float sm[256];
    float v = 0.f;
    for (int i = threadIdx.x; i < 8192; i += 256)
        v += TINV + logf(S[i]) - pos[i];
    sm[threadIdx.x] = v;
    __syncthreads();
    for (int o = 128; o; o >>= 1) {
        if (threadIdx.x < o) sm[threadIdx.x] += sm[threadIdx.x + o];
        __syncthreads();
    }
    if (threadIdx.x == 0) out[0] = sm[0] * (1.0f / 8192.0f);
}

// ================= launch =====================================================
extern "C" void kernel_launch(void* const* d_in, const int* in_sizes, int n_in,
                              void* d_out, int out_size)
{
    const float* x1 = (const float*)d_in[0];
    const float* x2 = (const float*)d_in[1];
    const float* W0 = (const float*)d_in[2];
    const float* b0 = (const float*)d_in[3];
    const float* W1 = (const float*)d_in[4];
    const float* b1 = (const float*)d_in[5];
    const float* W2 = (const float*)d_in[6];
    const float* b2 = (const float*)d_in[7];
    float* out = (float*)d_out;

    __half *x16, *w0t, *w1e, *w2t, *w12, *a0;
    __nv_bfloat16 *fhi, *flo;
    float *feat, *pos, *S, *b12, *w12p, *featp;
    cudaGetSymbolAddress((void**)&x16, g_x16);
    cudaGetSymbolAddress((void**)&w0t, g_w0t);
    cudaGetSymbolAddress((void**)&w1e, g_w1e);
    cudaGetSymbolAddress((void**)&w2t, g_w2t);
    cudaGetSymbolAddress((void**)&w12, g_w12);
    cudaGetSymbolAddress((void**)&w12p, g_w12p);
    cudaGetSymbolAddress((void**)&a0, g_a0);
    cudaGetSymbolAddress((void**)&featp, g_featp);
    cudaGetSymbolAddress((void**)&fhi, g_fhi);
    cudaGetSymbolAddress((void**)&flo, g_flo);
    cudaGetSymbolAddress((void**)&feat, g_feat);
    cudaGetSymbolAddress((void**)&pos, g_pos);
    cudaGetSymbolAddress((void**)&S, g_S);
    cudaGetSymbolAddress((void**)&b12, g_b12);

    cudaFuncSetAttribute(gemm_f16<true>,
                         cudaFuncAttributeMaxDynamicSharedMemorySize, GEMM_SMEM);
    cudaFuncSetAttribute(gemm_w12,
                         cudaFuncAttributeMaxDynamicSharedMemorySize, GEMM_SMEM);
    cudaFuncSetAttribute(gemm_head,
                         cudaFuncAttributeMaxDynamicSharedMemorySize, HEAD_SMEM);
    cudaFuncSetAttribute(loss_mma,
                         cudaFuncAttributeMaxDynamicSharedMemorySize, LOSS_SMEM);

    // ---- weight prep (fp16) ----
    tsplit16_kernel<<<dim3(64, 64), 256>>>(W0, w0t, 2048, 2048);
    tsplit16_kernel<<<dim3(4, 64), 256>>>(W2, w2t, 2048, 128);
    split16_kernel<<<(2048 * 2048 / 4) / 256, 256>>>(
        (const float4*)W1, (uint2*)w1e);

    gemm_w12<<<dim3(8, 16), 256, GEMM_SMEM>>>(w2t, w1e, w12p);
    w12_reduce<<<(128 * 2048 / 4) / 256, 256>>>(w12p, w12);
    b12_kernel<<<128, 256>>>(b1, W2, b2, b12);

    // ---- input cast (both views -> M=8192 fp16) ----
    const int NSPLIT = (4096 * 2048 / 4) / 256;
    split16_kernel<<<NSPLIT, 256>>>((const float4*)x1, (uint2*)x16);
    split16_kernel<<<NSPLIT, 256>>>((const float4*)x2,
                                    (uint2*)(x16 + (long)4096 * 2048));

    // ---- collapsed MLP ----
    gemm_f16<true><<<dim3(64, 16), 256, GEMM_SMEM>>>(x16, w0t, b0, a0);
    gemm_head<<<dim3(2, 128), 256, HEAD_SMEM>>>(a0, w12, featp);

    normalize_kernel<<<1024, 256>>>(featp, featp + (long)8192 * 128, b12,
                                    feat, fhi, flo);
    pos_kernel<<<1024, 256>>>(feat, pos, S);
    loss_mma<<<dim3(2, 64), 256, LOSS_SMEM>>>(fhi, flo, S);
    final_kernel<<<1, 256>>>(S, pos, out);
}

// round 17
// speedup vs baseline: 1.4549x; 1.3602x over previous
#include <cuda_runtime.h>
#include <cuda_fp16.h>
#include <cuda_bf16.h>
#include <stdint.h>
#include <math.h>

#define TINV 14.2857142857142857f   /* 1 / 0.07 */
#define K1E  20.6099291083577f      /* TINV * log2(e) */

// -------- scratch (no allocations allowed) --------
static __device__ __half g_x16[8192 * 2048];
static __device__ __half g_w0t[2048 * 2048];
static __device__ __half g_w1e[2048 * 2048];
static __device__ __half g_w2t[128 * 2048];
static __device__ __half g_w12[128 * 2048];
static __device__ float  g_w12p[8 * 128 * 2048];
static __device__ __half g_a0[8192 * 2048];
static __device__ float  g_featp[2 * 8192 * 128];
static __device__ float  g_b12[128];
static __device__ float  g_feat[8192 * 128];
static __device__ __half g_f16f[8192 * 128];
static __device__ float g_pos[8192];
static __device__ float g_S[8192];

// ======================= PTX helpers (baseline ISA only) =====================
__device__ __forceinline__ void cp_async16(unsigned int saddr, const void* gptr) {
    asm volatile("cp.async.ca.shared.global [%0], [%1], 16;" :: "r"(saddr), "l"(gptr));
}
__device__ __forceinline__ void cp_commit() {
    asm volatile("cp.async.commit_group;");
}
__device__ __forceinline__ unsigned int smem_u32(const void* p) {
    unsigned int a;
    asm("{ .reg .u64 t; cvta.to.shared.u64 t, %1; cvt.u32.u64 %0, t; }" : "=r"(a) : "l"(p));
    return a;
}
__device__ __forceinline__ void ldmat4(unsigned int* r, unsigned int addr) {
    asm volatile("ldmatrix.sync.aligned.m8n8.x4.shared.b16 {%0,%1,%2,%3}, [%4];"
        : "=r"(r[0]), "=r"(r[1]), "=r"(r[2]), "=r"(r[3]) : "r"(addr));
}
__device__ __forceinline__ void hmma(float* d, const unsigned int* a,
                                     unsigned int b0, unsigned int b1) {
    asm volatile(
        "mma.sync.aligned.m16n8k16.row.col.f32.f16.f16.f32 "
        "{%0,%1,%2,%3}, {%4,%5,%6,%7}, {%8,%9}, {%0,%1,%2,%3};"
        : "+f"(d[0]), "+f"(d[1]), "+f"(d[2]), "+f"(d[3])
        : "r"(a[0]), "r"(a[1]), "r"(a[2]), "r"(a[3]), "r"(b0), "r"(b1));
}

// ======================= fp16 warp-MMA GEMM (128x128) ========================
// 4-stage cp.async ring + wait_group 2, ONE barrier per chunk, 2 CTAs/SM.
#define ROWB 80
#define F_A 0
#define F_B (128 * ROWB)            /* 10240 */
#define FSTAGE (2 * 128 * ROWB)     /* 20480 */
#define SMEM_BIAS 0
#define SMEM_STAGE0 1024
#define GEMM_SMEM (SMEM_STAGE0 + 4 * FSTAGE)   /* 82944 */

template <bool RELU>
__global__ __launch_bounds__(256, 2) void gemm_f16(
    const __half* __restrict__ A, const __half* __restrict__ B,
    const float* __restrict__ bias, __half* __restrict__ C)
{
    extern __shared__ char smem[];
    const unsigned int sb = smem_u32(smem);
    const int tid  = threadIdx.x;
    const int lane = tid & 31;
    const int wid  = tid >> 5;
    const int wm   = wid >> 1;
    const int wn   = wid & 1;
    const int row0 = blockIdx.x * 128;
    const int col0 = blockIdx.y * 128;
    const int K = 2048;
    const int NKT = 64;

    if (tid < 128) ((float*)(smem + SMEM_BIAS))[tid] = bias[col0 + tid];

    const int srow = tid >> 1;
    const int shal = tid & 1;
    const __half* gA = A + (long)(row0 + srow) * K + shal * 16;
    const __half* gB = B + (long)(col0 + srow) * K + shal * 16;
    const unsigned int sro = srow * ROWB + shal * 32;

#define LOAD_STAGE(stg, k0) do { \
        cp_async16((stg) + F_A + sro,      gA + (k0)); \
        cp_async16((stg) + F_A + sro + 16, gA + (k0) + 8); \
        cp_async16((stg) + F_B + sro,      gB + (k0)); \
        cp_async16((stg) + F_B + sro + 16, gB + (k0) + 8); \
    } while (0)

#pragma unroll
    for (int b = 0; b < 3; b++) {
        LOAD_STAGE(sb + SMEM_STAGE0 + b * FSTAGE, b * 32);
        cp_commit();
    }

    float acc[2][8][4];
#pragma unroll
    for (int i = 0; i < 2; i++)
#pragma unroll
        for (int j = 0; j < 8; j++)
#pragma unroll
            for (int q = 0; q < 4; q++) acc[i][j][q] = 0.f;

    const unsigned int a_row  = lane & 15;
    const unsigned int a_koff = (lane >> 4) * 16;
    const unsigned int b_row  = (lane & 7) + ((lane >> 4) & 1) * 8;
    const unsigned int b_koff = ((lane >> 3) & 1) * 16;

    for (int kt = 0; kt < NKT; kt++) {
        const unsigned int stg = sb + SMEM_STAGE0 + (kt & 3) * FSTAGE;
        asm volatile("cp.async.wait_group 2;" ::: "memory");
        __syncthreads();

        if (kt + 3 < NKT) {
            const unsigned int pst = sb + SMEM_STAGE0 + ((kt + 3) & 3) * FSTAGE;
            LOAD_STAGE(pst, (kt + 3) * 32);
        }
        cp_commit();

#pragma unroll
        for (int s = 0; s < 2; s++) {
            const unsigned int kb = s * 32;
            unsigned int ah[2][4];
#pragma unroll
            for (int ma = 0; ma < 2; ma++) {
                unsigned int roff = (wm * 32 + ma * 16 + a_row) * ROWB + kb + a_koff;
                ldmat4(ah[ma], stg + F_A + roff);
            }
            unsigned int bh[4][4];
#pragma unroll
            for (int nb = 0; nb < 4; nb++) {
                unsigned int roff = (wn * 64 + nb * 16 + b_row) * ROWB + kb + b_koff;
                ldmat4(bh[nb], stg + F_B + roff);
            }
#pragma unroll
            for (int ma = 0; ma < 2; ma++)
#pragma unroll
                for (int na = 0; na < 8; na++)
                    hmma(acc[ma][na], ah[ma],
                         bh[na >> 1][(na & 1) * 2], bh[na >> 1][(na & 1) * 2 + 1]);
        }
    }

    const float* bs = (const float*)(smem + SMEM_BIAS);
    const int ccol = wn * 64;
#pragma unroll
    for (int ma = 0; ma < 2; ma++) {
#pragma unroll
        for (int na = 0; na < 8; na++) {
            int c  = ccol + na * 8 + (lane & 3) * 2;
            int r1 = row0 + wm * 32 + ma * 16 + (lane >> 2);
            int r2 = r1 + 8;
            float v0 = acc[ma][na][0] + bs[c];
            float v1 = acc[ma][na][1] + bs[c + 1];
            float v2 = acc[ma][na][2] + bs[c];
            float v3 = acc[ma][na][3] + bs[c + 1];
            if (RELU) {
                v0 = fmaxf(v0, 0.f); v1 = fmaxf(v1, 0.f);
                v2 = fmaxf(v2, 0.f); v3 = fmaxf(v3, 0.f);
            }
            *(__half2*)&C[(long)r1 * 2048 + col0 + c] = __floats2half2_rn(v0, v1);
            *(__half2*)&C[(long)r2 * 2048 + col0 + c] = __floats2half2_rn(v2, v3);
        }
    }
#undef LOAD_STAGE
}

// ======================= W12 split-K fp16 GEMM: grid (8, 16) =================
__global__ __launch_bounds__(256, 2) void gemm_w12(
    const __half* __restrict__ A, const __half* __restrict__ B,
    float* __restrict__ Cp)
{
    extern __shared__ char smem[];
    const unsigned int sb = smem_u32(smem);
    const int tid  = threadIdx.x;
    const int lane = tid & 31;
    const int wid  = tid >> 5;
    const int wm   = wid >> 1;
    const int wn   = wid & 1;
    const int col0 = blockIdx.y * 128;
    const int kbase = blockIdx.x * 256;
    const int K = 2048;
    const int NKT = 8;

    const int srow = tid >> 1;
    const int shal = tid & 1;
    const __half* gA = A + (long)srow * K + kbase + shal * 16;
    const __half* gB = B + (long)(col0 + srow) * K + kbase + shal * 16;
    const unsigned int sro = srow * ROWB + shal * 32;

#define LOAD_STAGE(stg, k0) do { \
        cp_async16((stg) + F_A + sro,      gA + (k0)); \
        cp_async16((stg) + F_A + sro + 16, gA + (k0) + 8); \
        cp_async16((stg) + F_B + sro,      gB + (k0)); \
        cp_async16((stg) + F_B + sro + 16, gB + (k0) + 8); \
    } while (0)

#pragma unroll
    for (int b = 0; b < 3; b++) {
        LOAD_STAGE(sb + SMEM_STAGE0 + b * FSTAGE, b * 32);
        cp_commit();
    }

    float acc[2][8][4];
#pragma unroll
    for (int i = 0; i < 2; i++)
#pragma unroll
        for (int j = 0; j < 8; j++)
#pragma unroll
            for (int q = 0; q < 4; q++) acc[i][j][q] = 0.f;

    const unsigned int a_row  = lane & 15;
    const unsigned int a_koff = (lane >> 4) * 16;
    const unsigned int b_row  = (lane & 7) + ((lane >> 4) & 1) * 8;
    const unsigned int b_koff = ((lane >> 3) & 1) * 16;

    for (int kt = 0; kt < NKT; kt++) {
        const unsigned int stg = sb + SMEM_STAGE0 + (kt & 3) * FSTAGE;
        asm volatile("cp.async.wait_group 2;" ::: "memory");
        __syncthreads();

        if (kt + 3 < NKT) {
            const unsigned int pst = sb + SMEM_STAGE0 + ((kt + 3) & 3) * FSTAGE;
            LOAD_STAGE(pst, (kt + 3) * 32);
        }
        cp_commit();

#pragma unroll
        for (int s = 0; s < 2; s++) {
            const unsigned int kb = s * 32;
            unsigned int ah[2][4];
#pragma unroll
            for (int ma = 0; ma < 2; ma++) {
                unsigned int roff = (wm * 32 + ma * 16 + a_row) * ROWB + kb + a_koff;
                ldmat4(ah[ma], stg + F_A + roff);
            }
            unsigned int bh[4][4];
#pragma unroll
            for (int nb = 0; nb < 4; nb++) {
                unsigned int roff = (wn * 64 + nb * 16 + b_row) * ROWB + kb + b_koff;
                ldmat4(bh[nb], stg + F_B + roff);
            }
#pragma unroll
            for (int ma = 0; ma < 2; ma++)
#pragma unroll
                for (int na = 0; na < 8; na++)
                    hmma(acc[ma][na], ah[ma],
                         bh[na >> 1][(na & 1) * 2], bh[na >> 1][(na & 1) * 2 + 1]);
        }
    }

    float* out = Cp + (long)blockIdx.x * 128 * 2048;
#pragma unroll
    for (int ma = 0; ma < 2; ma++) {
#pragma unroll
        for (int na = 0; na < 8; na++) {
            int c  = col0 + wn * 64 + na * 8 + (lane & 3) * 2;
            int r1 = wm * 32 + ma * 16 + (lane >> 2);
            int r2 = r1 + 8;
            *(float2*)&out[(long)r1 * 2048 + c] =
                make_float2(acc[ma][na][0], acc[ma][na][1]);
            *(float2*)&out[(long)r2 * 2048 + c] =
                make_float2(acc[ma][na][2], acc[ma][na][3]);
        }
    }
#undef LOAD_STAGE
}

// =========== fixed-order reduce of 8 W12 slices -> fp16 ======================
__global__ __launch_bounds__(256) void w12_reduce(
    const float* __restrict__ Cp, __half* __restrict__ T)
{
    int i = blockIdx.x * 256 + threadIdx.x;
    float4 s = ((const float4*)Cp)[i];
#pragma unroll
    for (int k = 1; k < 8; k++) {
        float4 p = ((const float4*)(Cp + (long)k * 128 * 2048))[i];
        s.x += p.x; s.y += p.y; s.z += p.z; s.w += p.w;
    }
    __half2 h0 = __floats2half2_rn(s.x, s.y);
    __half2 h1 = __floats2half2_rn(s.z, s.w);
    uint2 o = {*(unsigned int*)&h0, *(unsigned int*)&h1};
    ((uint2*)T)[i] = o;
}

// =================== head GEMM fp16 split-K: grid (2, 128), 4 stages =========
#define H_A 0
#define H_B (64 * ROWB)
#define H_STAGE (H_B + 128 * ROWB)
#define HEAD_SMEM (1024 + 4 * H_STAGE)

__global__ __launch_bounds__(256, 2) void gemm_head(
    const __half* __restrict__ A, const __half* __restrict__ B,
    float* __restrict__ Cp)
{
    extern __shared__ char smem[];
    const unsigned int sb = smem_u32(smem);
    const int tid  = threadIdx.x;
    const int lane = tid & 31;
    const int wid  = tid >> 5;
    const int wm   = wid >> 2;
    const int wn   = wid & 3;
    const int row0 = blockIdx.y * 64;
    const int kbase = blockIdx.x * 1024;
    const int K = 2048;
    const int NKT = 32;

    const int sar = tid >> 2;
    const int saq = tid & 3;
    const __half* gA = A + (long)(row0 + sar) * K + kbase + saq * 8;
    const unsigned int sra = sar * ROWB + saq * 16;
    const int sbr = tid >> 1;
    const int sbh = tid & 1;
    const __half* gB = B + (long)sbr * K + kbase + sbh * 16;
    const unsigned int srb = sbr * ROWB + sbh * 32;

#define H_LOAD(stg, k0) do { \
        cp_async16((stg) + H_A + sra, gA + (k0)); \
        cp_async16((stg) + H_B + srb,      gB + (k0)); \
        cp_async16((stg) + H_B + srb + 16, gB + (k0) + 8); \
    } while (0)

#pragma unroll
    for (int b = 0; b < 3; b++) {
        H_LOAD(sb + SMEM_STAGE0 + b * H_STAGE, b * 32);
        cp_commit();
    }

    float acc[2][4][4];
#pragma unroll
    for (int i = 0; i < 2; i++)
#pragma unroll
        for (int j = 0; j < 4; j++)
#pragma unroll
            for (int q = 0; q < 4; q++) acc[i][j][q] = 0.f;

    const unsigned int a_row  = lane & 15;
    const unsigned int a_koff = (lane >> 4) * 16;
    const unsigned int b_row  = (lane & 7) + ((lane >> 4) & 1) * 8;
    const unsigned int b_koff = ((lane >> 3) & 1) * 16;

    for (int kt = 0; kt < NKT; kt++) {
        const unsigned int stg = sb + SMEM_STAGE0 + (kt & 3) * H_STAGE;
        asm volatile("cp.async.wait_group 2;" ::: "memory");
        __syncthreads();

        if (kt + 3 < NKT) {
            const unsigned int pst = sb + SMEM_STAGE0 + ((kt + 3) & 3) * H_STAGE;
            H_LOAD(pst, (kt + 3) * 32);
        }
        cp_commit();

#pragma unroll
        for (int s = 0; s < 2; s++) {
            const unsigned int kb = s * 32;
            unsigned int ah[2][4];
#pragma unroll
            for (int ma = 0; ma < 2; ma++) {
                unsigned int roff = (wm * 32 + ma * 16 + a_row) * ROWB + kb + a_koff;
                ldmat4(ah[ma], stg + H_A + roff);
            }
            unsigned int bh[2][4];
#pragma unroll
            for (int nb = 0; nb < 2; nb++) {
                unsigned int roff = (wn * 32 + nb * 16 + b_row) * ROWB + kb + b_koff;
                ldmat4(bh[nb], stg + H_B + roff);
            }
#pragma unroll
            for (int ma = 0; ma < 2; ma++)
#pragma unroll
                for (int na = 0; na < 4; na++)
                    hmma(acc[ma][na], ah[ma],
                         bh[na >> 1][(na & 1) * 2], bh[na >> 1][(na & 1) * 2 + 1]);
        }
    }

    float* out = Cp + (long)blockIdx.x * 8192 * 128;
#pragma unroll
    for (int ma = 0; ma < 2; ma++) {
#pragma unroll
        for (int na = 0; na < 4; na++) {
            int c  = wn * 32 + na * 8 + (lane & 3) * 2;
            int r1 = row0 + wm * 32 + ma * 16 + (lane >> 2);
            int r2 = r1 + 8;
            *(float2*)&out[(long)r1 * 128 + c] =
                make_float2(acc[ma][na][0], acc[ma][na][1]);
            *(float2*)&out[(long)r2 * 128 + c] =
                make_float2(acc[ma][na][2], acc[ma][na][3]);
        }
    }
#undef H_LOAD
}

// ======================= fp32 -> fp16 cast ====================================
__global__ __launch_bounds__(256) void split16_kernel(
    const float4* __restrict__ in, uint2* __restrict__ out)
{
    int i = blockIdx.x * 256 + threadIdx.x;
    float4 v = in[i];
    __half2 h0 = __floats2half2_rn(v.x, v.y);
    __half2 h1 = __floats2half2_rn(v.z, v.w);
    uint2 o = {*(unsigned int*)&h0, *(unsigned int*)&h1};
    out[i] = o;
}

// ============== W [R,C] -> W^T fp16 [C,R] =====================================
__global__ __launch_bounds__(256) void tsplit16_kernel(
    const float* __restrict__ W, __half* __restrict__ T, int R, int C)
{
    __shared__ float t[32][33];
    int lane = threadIdx.x % 32;
    int ty = threadIdx.x / 32;
    int x = blockIdx.x * 32 + lane;
    int y0 = blockIdx.y * 32;
#pragma unroll
    for (int i = 0; i < 4; i++)
        t[ty + 8 * i][lane] = W[(long)(y0 + ty + 8 * i) * C + x];
    __syncthreads();
    int xo = y0 + lane;
    int yo = blockIdx.x * 32;
#pragma unroll
    for (int i = 0; i < 4; i++)
        T[(long)(yo + ty + 8 * i) * R + xo] = __float2half_rn(t[lane][ty + 8 * i]);
}

// ================= b12[n] = sum_j b1[j] W2[j,n] + b2[n] ======================
__global__ __launch_bounds__(256) void b12_kernel(
    const float* __restrict__ b1, const float* __restrict__ W2,
    const float* __restrict__ b2, float* __restrict__ b12)
{
    __shared__ float sm[256];
    int n = blockIdx.x;
    float s = 0.f;
    for (int j = threadIdx.x; j < 2048; j += 256)
        s = fmaf(b1[j], W2[(long)j * 128 + n], s);
    sm[threadIdx.x] = s;
    __syncthreads();
    for (int o = 128; o; o >>= 1) {
        if (threadIdx.x < o) sm[threadIdx.x] += sm[threadIdx.x + o];
        __syncthreads();
    }
    if (threadIdx.x == 0) b12[n] = sm[0] + b2[n];
}

// ====== fused: feat = p0 + p1 + b12; L2-normalize; emit fp32 + fp16 ==========
__global__ __launch_bounds__(256) void normalize_kernel(
    const float* __restrict__ p0, const float* __restrict__ p1,
    const float* __restrict__ b12, float* __restrict__ f,
    __half* __restrict__ f16)
{
    int row  = blockIdx.x * 8 + (threadIdx.x >> 5);
    int lane = threadIdx.x & 31;
    int idx = row * 32 + lane;
    float4 a = ((const float4*)p0)[idx];
    float4 b = ((const float4*)p1)[idx];
    float4 bi = ((const float4*)b12)[lane];
    float4 v;
    v.x = a.x + b.x + bi.x;
    v.y = a.y + b.y + bi.y;
    v.z = a.z + b.z + bi.z;
    v.w = a.w + b.w + bi.w;
    float s = v.x * v.x + v.y * v.y + v.z * v.z + v.w * v.w;
#pragma unroll
    for (int o = 16; o; o >>= 1) s += __shfl_xor_sync(0xffffffffu, s, o);
    float r = rsqrtf(s);
    v.x *= r; v.y *= r; v.z *= r; v.w *= r;
    ((float4*)f)[idx] = v;
    __half2 h0 = __floats2half2_rn(v.x, v.y);
    __half2 h1 = __floats2half2_rn(v.z, v.w);
    uint2 o = {*(unsigned int*)&h0, *(unsigned int*)&h1};
    *(uint2*)&f16[row * 128 + lane * 4] = o;
}

// ================= positive-pair similarity + zero S ==========================
__global__ __launch_bounds__(256) void pos_kernel(
    const float* __restrict__ f, float* __restrict__ pos, float* __restrict__ S)
{
    int row  = blockIdx.x * 8 + (threadIdx.x >> 5);
    int lane = threadIdx.x & 31;
    int partner = (row + 4096) & 8191;
    float4 a = ((const float4*)f)[row * 32 + lane];
    float4 b = ((const float4*)f)[partner * 32 + lane];
    float s = a.x * b.x + a.y * b.y + a.z * b.z + a.w * b.w;
#pragma unroll
    for (int o = 16; o; o >>= 1) s += __shfl_xor_sync(0xffffffffu, s, o);
    if (lane == 0) { pos[row] = s * TINV; S[row] = 0.f; }
}

// ============ fp16 single-term tensorized sim + sum-of-exp ===================
// grid (2, 64). Rows persistent (1 array), 2-stage col ring (1 array each).
// Per fragment: ONE fp16 MMA (was 3 bf16). Row sums via 2 deterministic atomics.
#define ROW2 272
#define LAR  (128 * ROW2)           /* 34816 */
#define LS_A 0
#define LS_BST LAR
#define LS_RS  (3 * LAR)
#define LOSS_SMEM (3 * LAR + 1024)  /* 105472 */

__global__ __launch_bounds__(256) void loss_mma(
    const __half* __restrict__ f16, float* __restrict__ S)
{
    extern __shared__ char smem[];
    const unsigned int sb = smem_u32(smem);
    const int tid  = threadIdx.x;
    const int lane = tid & 31;
    const int wid  = tid >> 5;
    const int wm   = wid >> 1;
    const int wn   = wid & 1;
    const int r0   = blockIdx.y * 128;
    const int cbase = blockIdx.x * 4096;

    const int srow = tid >> 1;
    const int shal = tid & 1;
    const unsigned int sro = srow * ROW2 + shal * 128;

    // rows (persistent, single fp16 array: 128 rows x 256 B)
    {
        const __half* g = f16 + (long)(r0 + srow) * 128 + shal * 64;
#pragma unroll
        for (int c = 0; c < 8; c++)
            cp_async16(sb + LS_A + sro + c * 16, g + c * 8);
        cp_commit();
    }

#define LOAD_COL(s, ct) do { \
        unsigned int base = sb + LS_BST + (s) * LAR; \
        const __half* g = f16 + (long)(cbase + (ct) * 128 + srow) * 128 + shal * 64; \
        _Pragma("unroll") \
        for (int c = 0; c < 8; c++) \
            cp_async16(base + sro + c * 16, g + c * 8); \
        cp_commit(); \
    } while (0)

    LOAD_COL(0, 0);
    LOAD_COL(1, 1);

    float accS[4] = {0.f, 0.f, 0.f, 0.f};

    const unsigned int a_row  = lane & 15;
    const unsigned int a_koff = (lane >> 4) * 16;
    const unsigned int b_row  = (lane & 7) + ((lane >> 4) & 1) * 8;
    const unsigned int b_koff = ((lane >> 3) & 1) * 16;

    for (int ct = 0; ct < 32; ct++) {
        const unsigned int stg = sb + LS_BST + (ct & 1) * LAR;
        asm volatile("cp.async.wait_group 1;" ::: "memory");
        __syncthreads();

        float acc[2][8][4];
#pragma unroll
        for (int i = 0; i < 2; i++)
#pragma unroll
            for (int j = 0; j < 8; j++)
#pragma unroll
                for (int q = 0; q < 4; q++) acc[i][j][q] = 0.f;

#pragma unroll
        for (int s = 0; s < 8; s++) {
            const unsigned int kb = s * 32;
            unsigned int ah[2][4];
#pragma unroll
            for (int ma = 0; ma < 2; ma++) {
                unsigned int roff = (wm * 32 + ma * 16 + a_row) * ROW2 + kb + a_koff;
                ldmat4(ah[ma], sb + LS_A + roff);
            }
            unsigned int bh[4][4];
#pragma unroll
            for (int nb = 0; nb < 4; nb++) {
                unsigned int roff = (wn * 64 + nb * 16 + b_row) * ROW2 + kb + b_koff;
                ldmat4(bh[nb], stg + roff);
            }
#pragma unroll
            for (int ma = 0; ma < 2; ma++)
#pragma unroll
                for (int na = 0; na < 8; na++)
                    hmma(acc[ma][na], ah[ma],
                         bh[na >> 1][(na & 1) * 2], bh[na >> 1][(na & 1) * 2 + 1]);
        }

        const int c0 = cbase + ct * 128;
#pragma unroll
        for (int ma = 0; ma < 2; ma++) {
            int gi1 = r0 + wm * 32 + ma * 16 + (lane >> 2);
            int gi2 = gi1 + 8;
#pragma unroll
            for (int na = 0; na < 8; na++) {
                int gj = c0 + wn * 64 + na * 8 + (lane & 3) * 2;
                float e0 = exp2f(fmaf(acc[ma][na][0], K1E, -K1E));
                float e1 = exp2f(fmaf(acc[ma][na][1], K1E, -K1E));
                float e2 = exp2f(fmaf(acc[ma][na][2], K1E, -K1E));
                float e3 = exp2f(fmaf(acc[ma][na][3], K1E, -K1E));
                accS[ma * 2 + 0] += ((gi1 != gj)     ? e0 : 0.f)
                                  + ((gi1 != gj + 1) ? e1 : 0.f);
                accS[ma * 2 + 1] += ((gi2 != gj)     ? e2 : 0.f)
                                  + ((gi2 != gj + 1) ? e3 : 0.f);
            }
        }

        __syncthreads();
        if (ct + 2 < 32) LOAD_COL(ct & 1, ct + 2);
        else cp_commit();
    }

#pragma unroll
    for (int i = 0; i < 4; i++) {
        accS[i] += __shfl_xor_sync(0xffffffffu, accS[i], 1);
        accS[i] += __shfl_xor_sync(0xffffffffu, accS[i], 2);
    }
    __syncthreads();
    float* rs = (float*)(smem + LS_RS);
    if ((lane & 3) == 0) {
#pragma unroll
        for (int i = 0; i < 4; i++) {
            int rloc = wm * 32 + (i >> 1) * 16 + (i & 1) * 8 + (lane >> 2);
            rs[rloc * 2 + wn] = accS[i];
        }
    }
    __syncthreads();
    if (tid < 128)
        atomicAdd(&S[r0 + tid], rs[tid * 2] + rs[tid * 2 + 1]);
#undef LOAD_COL
}

// ================= final deterministic reduction ==============================
__global__ __launch_bounds__(256) void final_kernel(
    const float* __restrict__ S, const float* __restrict__ pos,
    float* __restrict__ out)
{
    __shared__ float sm[256];
    float v = 0.f;
    for (int i = threadIdx.x; i < 8192; i += 256)
        v += TINV + logf(S[i]) - pos[i];
    sm[threadIdx.x] = v;
    __syncthreads();
    for (int o = 128; o; o >>= 1) {
        if (threadIdx.x < o) sm[threadIdx.x] += sm[threadIdx.x + o];
        __syncthreads();
    }
    if (threadIdx.x == 0) out[0] = sm[0] * (1.0f / 8192.0f);
}

// ================= launch =====================================================
extern "C" void kernel_launch(void* const* d_in, const int* in_sizes, int n_in,
                              void* d_out, int out_size)
{
    const float* x1 = (const float*)d_in[0];
    const float* x2 = (const float*)d_in[1];
    const float* W0 = (const float*)d_in[2];
    const float* b0 = (const float*)d_in[3];
    const float* W1 = (const float*)d_in[4];
    const float* b1 = (const float*)d_in[5];
    const float* W2 = (const float*)d_in[6];
    const float* b2 = (const float*)d_in[7];
    float* out = (float*)d_out;

    __half *x16, *w0t, *w1e, *w2t, *w12, *a0, *f16f;
    float *feat, *pos, *S, *b12, *w12p, *featp;
    cudaGetSymbolAddress((void**)&x16, g_x16);
    cudaGetSymbolAddress((void**)&w0t, g_w0t);
    cudaGetSymbolAddress((void**)&w1e, g_w1e);
    cudaGetSymbolAddress((void**)&w2t, g_w2t);
    cudaGetSymbolAddress((void**)&w12, g_w12);
    cudaGetSymbolAddress((void**)&w12p, g_w12p);
    cudaGetSymbolAddress((void**)&a0, g_a0);
    cudaGetSymbolAddress((void**)&featp, g_featp);
    cudaGetSymbolAddress((void**)&f16f, g_f16f);
    cudaGetSymbolAddress((void**)&feat, g_feat);
    cudaGetSymbolAddress((void**)&pos, g_pos);
    cudaGetSymbolAddress((void**)&S, g_S);
    cudaGetSymbolAddress((void**)&b12, g_b12);

    cudaFuncSetAttribute(gemm_f16<true>,
                         cudaFuncAttributeMaxDynamicSharedMemorySize, GEMM_SMEM);
    cudaFuncSetAttribute(gemm_w12,
                         cudaFuncAttributeMaxDynamicSharedMemorySize, GEMM_SMEM);
    cudaFuncSetAttribute(gemm_head,
                         cudaFuncAttributeMaxDynamicSharedMemorySize, HEAD_SMEM);
    cudaFuncSetAttribute(loss_mma,
                         cudaFuncAttributeMaxDynamicSharedMemorySize, LOSS_SMEM);

    // ---- weight prep (fp16) ----
    tsplit16_kernel<<<dim3(64, 64), 256>>>(W0, w0t, 2048, 2048);
    tsplit16_kernel<<<dim3(4, 64), 256>>>(W2, w2t, 2048, 128);
    split16_kernel<<<(2048 * 2048 / 4) / 256, 256>>>(
        (const float4*)W1, (uint2*)w1e);

    gemm_w12<<<dim3(8, 16), 256, GEMM_SMEM>>>(w2t, w1e, w12p);
    w12_reduce<<<(128 * 2048 / 4) / 256, 256>>>(w12p, w12);
    b12_kernel<<<128, 256>>>(b1, W2, b2, b12);

    // ---- input cast (both views -> M=8192 fp16) ----
    const int NSPLIT = (4096 * 2048 / 4) / 256;
    split16_kernel<<<NSPLIT, 256>>>((const float4*)x1, (uint2*)x16);
    split16_kernel<<<NSPLIT, 256>>>((const float4*)x2,
                                    (uint2*)(x16 + (long)4096 * 2048));

    // ---- collapsed MLP ----
    gemm_f16<true><<<dim3(64, 16), 256, GEMM_SMEM>>>(x16, w0t, b0, a0);
    gemm_head<<<dim3(2, 128), 256, HEAD_SMEM>>>(a0, w12, featp);

    normalize_kernel<<<1024, 256>>>(featp, featp + (long)8192 * 128, b12,
                                    feat, f16f);
    pos_kernel<<<1024, 256>>>(feat, pos, S);
    loss_mma<<<dim3(2, 64), 256, LOSS_SMEM>>>(f16f, S);
    final_kernel<<<1, 256>>>(S, pos, out);
}